// round 12
// baseline (speedup 1.0000x reference)
#include <cuda_runtime.h>

#define HH 2048
#define WW 2048
#define HWT (HH*WW)
#define RD 7
#define RG 60
#define KSEL 4195u          /* (H*W)//1000 + 1 : rank of threshold (1-based from top) */
#define OMEGA 0.95f
#define EPSG 1e-4f

// ---------------- scratch (device globals; no allocation) ----------------
__device__ float    g_dch[HWT];            // horizontal-min intermediate
__device__ float    g_dc[HWT];             // dark channel
__device__ float    g_vsum[10*HWT];        // 10 vertically box-summed planes (160MB)
__device__ unsigned g_hist1[2048];         // coarse bins: float bits >> 19
__device__ unsigned g_hist2b[524288];      // fine bins: low 19 bits (within coarse bin)
__device__ unsigned g_chunk[1024];         // 512-bin chunk sums of g_hist2b
__device__ unsigned g_selKey;
__device__ unsigned g_selRank;
__device__ float    g_thres;
__device__ unsigned g_cnt;
__device__ float    g_sumr, g_sumg, g_sumb;
__device__ float    g_avg, g_invavg;

// ---------------- init: zero histograms / accumulators ----------------
__global__ void k_init() {
    int i = blockIdx.x * blockDim.x + threadIdx.x;
    if (i < 524288) g_hist2b[i] = 0u;
    if (i < 2048)   g_hist1[i]  = 0u;
    if (i < 1024)   g_chunk[i]  = 0u;
    if (i == 0) {
        g_cnt = 0u; g_sumr = 0.f; g_sumg = 0.f; g_sumb = 0.f;
        g_selKey = 0u; g_selRank = 0u; g_thres = 0.f;
    }
}

// ---------------- channel-min + horizontal min (r=7) ----------------
__global__ void __launch_bounds__(256) k_cmin_hmin(const float* __restrict__ x) {
    __shared__ float s[256 + 2*RD];
    int row = blockIdx.y;
    int x0  = blockIdx.x * 256;
    int t   = threadIdx.x;
    for (int i = t; i < 256 + 2*RD; i += 256) {
        int xx = x0 - RD + i;
        float v = 1e30f;
        if (xx >= 0 && xx < WW) {
            float r = x[0*HWT + row*WW + xx];
            float g = x[1*HWT + row*WW + xx];
            float b = x[2*HWT + row*WW + xx];
            v = fminf(r, fminf(g, b));
        }
        s[i] = v;
    }
    __syncthreads();
    float m = s[t];
#pragma unroll
    for (int j = 1; j <= 2*RD; j++) m = fminf(m, s[t + j]);
    g_dch[row*WW + x0 + t] = m;
}

// ---------------- vertical min (r=7) + fused coarse histogram ----------------
__global__ void __launch_bounds__(256) k_vmin_hist() {
    __shared__ float s[16 + 2*RD][256];
    __shared__ unsigned sh[2048];
    int t = threadIdx.x;
    for (int i = t; i < 2048; i += 256) sh[i] = 0u;
    int xx = blockIdx.x * 256 + t;
    int y0 = blockIdx.y * 16;
    for (int r = 0; r < 16 + 2*RD; r++) {
        int yy = y0 - RD + r;
        s[r][t] = (yy >= 0 && yy < HH) ? g_dch[yy*WW + xx] : 1e30f;
    }
    __syncthreads();
    int lane = t & 31;
    for (int k = 0; k < 16; k++) {
        float m = s[k][t];
#pragma unroll
        for (int j = 1; j <= 2*RD; j++) m = fminf(m, s[k + j][t]);
        g_dc[(y0 + k)*WW + xx] = m;
        unsigned key = __float_as_uint(m) >> 19;   // < 2048 for dc in [0,1)
        unsigned prev = __shfl_up_sync(0xffffffffu, key, 1);
        bool leader = (lane == 0) || (key != prev);
        unsigned bal = __ballot_sync(0xffffffffu, leader);
        if (leader) {
            unsigned above = (lane == 31) ? 0u : (bal >> (lane + 1));
            int run = above ? __ffs((int)above) : (32 - lane);
            atomicAdd(&sh[key], (unsigned)run);
        }
    }
    __syncthreads();
    for (int i = t; i < 2048; i += 256) {
        unsigned v = sh[i];
        if (v) atomicAdd(&g_hist1[i], v);
    }
}

// ---------------- find coarse bin containing the KSEL-th largest ----------------
__global__ void __launch_bounds__(256) k_scan1() {
    __shared__ unsigned part[256];
    int t = threadIdx.x;
    int hi = 2047 - 8 * t;
    unsigned sum = 0;
#pragma unroll
    for (int j = 0; j < 8; j++) sum += g_hist1[hi - j];
    part[t] = sum;
    __syncthreads();
    if (t == 0) {
        unsigned cum = 0; int sel = 0;
        for (int i = 0; i < 256; i++) {
            if (cum + part[i] >= KSEL) { sel = i; break; }
            cum += part[i];
        }
        int hb = 2047 - 8 * sel;
        for (int j = 0; j < 8; j++) {
            unsigned h = g_hist1[hb - j];
            if (cum + h >= KSEL) {
                g_selKey = (unsigned)(hb - j);
                g_selRank = KSEL - cum;
                break;
            }
            cum += h;
        }
    }
}

// ---------------- histogram pass 2: low 19 bits within selected bin (uint4) ----------------
__global__ void k_hist2() {
    unsigned B = g_selKey;
    const uint4* __restrict__ dc4 = reinterpret_cast<const uint4*>(g_dc);
    int tid = blockIdx.x * blockDim.x + threadIdx.x;
    int stride = gridDim.x * blockDim.x;
    for (int i = tid; i < HWT/4; i += stride) {
        uint4 v = dc4[i];
        if ((v.x >> 19) == B) atomicAdd(&g_hist2b[v.x & 0x7FFFFu], 1u);
        if ((v.y >> 19) == B) atomicAdd(&g_hist2b[v.y & 0x7FFFFu], 1u);
        if ((v.z >> 19) == B) atomicAdd(&g_hist2b[v.z & 0x7FFFFu], 1u);
        if ((v.w >> 19) == B) atomicAdd(&g_hist2b[v.w & 0x7FFFFu], 1u);
    }
}

// ---------------- reduce fine histogram into 1024 chunk sums (coalesced) ----------------
__global__ void __launch_bounds__(128) k_chunks() {
    __shared__ unsigned w[4];
    int b = blockIdx.x, t = threadIdx.x;
    unsigned s = 0;
#pragma unroll
    for (int k = 0; k < 4; k++) s += g_hist2b[b * 512 + k * 128 + t];
#pragma unroll
    for (int o = 16; o > 0; o >>= 1) s += __shfl_down_sync(0xffffffffu, s, o);
    if ((t & 31) == 0) w[t >> 5] = s;
    __syncthreads();
    if (t == 0) g_chunk[b] = w[0] + w[1] + w[2] + w[3];
}

// ---------------- select chunk, then exact fine bin ----------------
__global__ void __launch_bounds__(1024) k_scan2() {
    __shared__ unsigned sc[1024];
    __shared__ unsigned sb[512];
    __shared__ int selC;
    __shared__ unsigned selR;
    unsigned K = g_selRank;
    int t = threadIdx.x;
    sc[t] = g_chunk[t];                     // coalesced
    __syncthreads();
    if (t == 0) {
        unsigned cum = 0;
        for (int j = 1023; j >= 0; j--) {
            unsigned h = sc[j];
            if (cum + h >= K) { selC = j; selR = K - cum; break; }
            cum += h;
        }
    }
    __syncthreads();
    int c = selC;
    if (t < 512) sb[t] = g_hist2b[c * 512 + t];   // coalesced
    __syncthreads();
    if (t == 0) {
        unsigned K2 = selR;
        unsigned cum = 0;
        for (int j = 511; j >= 0; j--) {
            unsigned h = sb[j];
            if (cum + h >= K2) {
                g_thres = __uint_as_float((g_selKey << 19) | (unsigned)(c * 512 + j));
                break;
            }
            cum += h;
        }
    }
}

// ---------------- masked sums for atmospheric light (float4 dc) ----------------
__global__ void k_mask(const float* __restrict__ x) {
    float th = g_thres;
    const float4* __restrict__ dc4 = reinterpret_cast<const float4*>(g_dc);
    int tid = blockIdx.x * blockDim.x + threadIdx.x;
    int stride = gridDim.x * blockDim.x;
    unsigned cnt = 0; float sr = 0.f, sg = 0.f, sb = 0.f;
    for (int i = tid; i < HWT/4; i += stride) {
        float4 d = dc4[i];
        int base = i * 4;
#pragma unroll
        for (int j = 0; j < 4; j++) {
            float dv = (j == 0) ? d.x : (j == 1) ? d.y : (j == 2) ? d.z : d.w;
            if (dv >= th) {
                cnt++;
                sr += x[base + j];
                sg += x[HWT + base + j];
                sb += x[2*HWT + base + j];
            }
        }
    }
#pragma unroll
    for (int o = 16; o > 0; o >>= 1) {
        cnt += __shfl_down_sync(0xffffffffu, cnt, o);
        sr  += __shfl_down_sync(0xffffffffu, sr,  o);
        sg  += __shfl_down_sync(0xffffffffu, sg,  o);
        sb  += __shfl_down_sync(0xffffffffu, sb,  o);
    }
    if ((threadIdx.x & 31) == 0) {
        atomicAdd(&g_cnt, cnt);
        atomicAdd(&g_sumr, sr);
        atomicAdd(&g_sumg, sg);
        atomicAdd(&g_sumb, sb);
    }
}

__global__ void k_avg() {
    float c = (float)g_cnt;
    float avg = (0.299f * g_sumr + 0.587f * g_sumg + 0.114f * g_sumb) / c;
    g_avg = avg;
    g_invavg = 1.0f / avg;
}

// ---------------- helpers for the vertical pass (float2) ----------------
__device__ __forceinline__ void vload2(const float* __restrict__ x, int yy, int c,
                                       float2 r[4]) {
    int o = yy * WW + c;
    r[0] = *(const float2*)(x + o);
    r[1] = *(const float2*)(x + HWT + o);
    r[2] = *(const float2*)(x + 2*HWT + o);
    r[3] = *(const float2*)(g_dc + o);
}

__device__ __forceinline__ void vplanes2(const float2 r[4], float inva, float2 v[10]) {
    float px = fmaf(-OMEGA * inva, r[3].x, 1.0f);
    float py = fmaf(-OMEGA * inva, r[3].y, 1.0f);
    v[0] = make_float2(px, py);
    v[1] = r[0]; v[2] = r[1]; v[3] = r[2];
    v[4] = make_float2(px * r[0].x, py * r[0].y);
    v[5] = make_float2(px * r[1].x, py * r[1].y);
    v[6] = make_float2(px * r[2].x, py * r[2].y);
    v[7] = make_float2(r[0].x * r[0].x, r[0].y * r[0].y);
    v[8] = make_float2(r[1].x * r[1].x, r[1].y * r[1].y);
    v[9] = make_float2(r[2].x * r[2].x, r[2].y * r[2].y);
}

// ---------------- vertical rolling box sums of the 10 planes (float2) ----------------
#define VS 16
__global__ void __launch_bounds__(256) k_vpass(const float* __restrict__ x) {
    int c  = (blockIdx.x * 256 + threadIdx.x) * 2;
    int y0 = blockIdx.y * VS;
    float inva = g_invavg;
    float2 s[10];
#pragma unroll
    for (int p = 0; p < 10; p++) s[p] = make_float2(0.f, 0.f);

    bool interior = (y0 >= RG + 1) && (y0 + VS - 1 + RG < HH);

    int ylo = y0 - RG; if (ylo < 0) ylo = 0;
    int yhi = y0 + RG; if (yhi > HH - 1) yhi = HH - 1;
#pragma unroll 4
    for (int yy = ylo; yy <= yhi; yy++) {
        float2 r[4]; vload2(x, yy, c, r);
        float2 v[10]; vplanes2(r, inva, v);
#pragma unroll
        for (int p = 0; p < 10; p++) { s[p].x += v[p].x; s[p].y += v[p].y; }
    }

    if (interior) {
        float2 ra[4], rs[4];
        vload2(x, y0 + 1 + RG, c, ra);
        vload2(x, y0 - RG, c, rs);
#pragma unroll
        for (int p = 0; p < 10; p++)
            *(float2*)(g_vsum + p*HWT + y0*WW + c) = s[p];
        for (int k = 1; k < VS; k++) {
            int y = y0 + k;
            float2 vA[10], vS[10];
            vplanes2(ra, inva, vA);
            vplanes2(rs, inva, vS);
#pragma unroll
            for (int p = 0; p < 10; p++) {
                s[p].x += vA[p].x - vS[p].x;
                s[p].y += vA[p].y - vS[p].y;
            }
            if (k + 1 < VS) {
                vload2(x, y + 1 + RG, c, ra);
                vload2(x, y - RG, c, rs);
            }
#pragma unroll
            for (int p = 0; p < 10; p++)
                *(float2*)(g_vsum + p*HWT + y*WW + c) = s[p];
        }
    } else {
        for (int k = 0; k < VS; k++) {
            int y = y0 + k;
            if (k > 0) {
                int ya = y + RG;
                if (ya < HH) {
                    float2 r[4]; vload2(x, ya, c, r);
                    float2 v[10]; vplanes2(r, inva, v);
#pragma unroll
                    for (int p = 0; p < 10; p++) { s[p].x += v[p].x; s[p].y += v[p].y; }
                }
                int yr = y - RG - 1;
                if (yr >= 0) {
                    float2 r[4]; vload2(x, yr, c, r);
                    float2 v[10]; vplanes2(r, inva, v);
#pragma unroll
                    for (int p = 0; p < 10; p++) { s[p].x -= v[p].x; s[p].y -= v[p].y; }
                }
            }
#pragma unroll
            for (int p = 0; p < 10; p++)
                *(float2*)(g_vsum + p*HWT + y*WW + c) = s[p];
        }
    }
}

// ---------------- horizontal pass: bulk load + warp-local scans + epilogue ----------------
// one block per half-row: 1024 outputs, segment 1144 padded to 1152 (36 warps)
#define SEG 1144
#define SEGP 1152
__global__ void __launch_bounds__(256) k_hfinal(const float* __restrict__ x,
                                                float* __restrict__ out) {
    __shared__ float sps[10*SEGP];       // warp-local inclusive scans (in place)
    __shared__ float swt[10*36];         // warp totals
    int row = blockIdx.y;
    int c0  = blockIdx.x * 1024;
    int s0  = c0 - RG;
    int t = threadIdx.x, lane = t & 31, w = t >> 5;

    // phase 1: bulk load 10 planes x SEGP (zero-padded) — 45 independent loads/thread
    const float* __restrict__ vs = g_vsum + row * WW;
#pragma unroll
    for (int i = 0; i < 45; i++) {
        int idx = i * 256 + t;           // < 11520
        int pl  = idx / SEGP;
        int L   = idx - pl * SEGP;
        int gc  = s0 + L;
        float v = 0.f;
        if (L < SEG && gc >= 0 && gc < WW) v = vs[pl * HWT + gc];
        sps[idx] = v;
    }
    __syncthreads();

    // phase 2: 360 independent warp-local inclusive scans (no cross-warp carries)
    // warp w handles segments w, w+8, ... (45 per warp)
#pragma unroll
    for (int i = 0; i < 45; i++) {
        int seg = i * 8 + w;             // < 360
        int idx = seg * 32 + lane;
        float v = sps[idx];
#pragma unroll
        for (int o = 1; o < 32; o <<= 1) {
            float n = __shfl_up_sync(0xffffffffu, v, o);
            if (lane >= o) v += n;
        }
        sps[idx] = v;
        if (lane == 31) swt[seg] = v;    // swt[pl*36 + local_seg], since SEGP/32=36
    }
    __syncthreads();

    // phase 3: windowed diff via warp-local scans + totals, then epilogue
    float avg = g_avg;
    int ny = min(row + RG, HH - 1) - max(row - RG, 0) + 1;
#pragma unroll
    for (int j = 0; j < 4; j++) {
        int L = t + j * 256;             // 0..1023
        int gc = c0 + L;
        int hi = L + 2*RG;               // in [120, 1143]
        int lo = L - 1;                  // in [-1, 1022]
        int jhi = hi >> 5, jlo = (lo >= 0) ? (lo >> 5) : -1;
        float wv[10];
#pragma unroll
        for (int p = 0; p < 10; p++) {
            float sum = sps[p*SEGP + hi];
            if (lo >= 0) {
                if (jlo == jhi) sum -= sps[p*SEGP + lo];
                else {
                    sum -= sps[p*SEGP + lo];
                    for (int q = jlo; q < jhi; q++) sum += swt[p*36 + q];
                }
            } else {
                for (int q = 0; q < jhi; q++) sum += swt[p*36 + q];
            }
            wv[p] = sum;
        }
        int nx = min(gc + RG, WW - 1) - max(gc - RG, 0) + 1;
        float invN = __fdividef(1.0f, (float)(nx * ny));
        float mp = wv[0] * invN;
        int base = row * WW + gc;
#pragma unroll
        for (int ch = 0; ch < 3; ch++) {
            float mi  = wv[1 + ch] * invN;
            float mpi = wv[4 + ch] * invN;
            float mii = wv[7 + ch] * invN;
            float cip = mpi - mp * mi;
            float cii = mii - mi * mi;
            float a = __fdividef(cip, cii + EPSG);
            float b = mp - a * mi;
            float xi = x[ch * HWT + base];
            float rt = fminf(fmaxf(a * xi + b, 0.0f), 1.0f);
            rt = fmaxf(rt, 0.1f);
            float yv = __fdividef(xi - avg, rt) + avg;
            out[ch * HWT + base] = fminf(fmaxf(yv, 0.0f), 1.0f);
        }
    }
}

// ---------------- launch ----------------
extern "C" void kernel_launch(void* const* d_in, const int* in_sizes, int n_in,
                              void* d_out, int out_size) {
    const float* x = (const float*)d_in[0];
    float* out = (float*)d_out;

    k_init<<<2048, 256>>>();
    k_cmin_hmin<<<dim3(8, 2048), 256>>>(x);
    k_vmin_hist<<<dim3(8, 128), 256>>>();
    k_scan1<<<1, 256>>>();
    k_hist2<<<1024, 256>>>();
    k_chunks<<<1024, 128>>>();
    k_scan2<<<1, 1024>>>();
    k_mask<<<1024, 256>>>(x);
    k_avg<<<1, 1>>>();
    k_vpass<<<dim3(4, 128), 256>>>(x);
    k_hfinal<<<dim3(2, 2048), 256>>>(x, out);
}

// round 13
// speedup vs baseline: 1.0017x; 1.0017x over previous
#include <cuda_runtime.h>

#define HH 2048
#define WW 2048
#define HWT (HH*WW)
#define RD 7
#define RG 60
#define KSEL 4195u          /* (H*W)//1000 + 1 : rank of threshold (1-based from top) */
#define OMEGA 0.95f
#define EPSG 1e-4f

// ---------------- scratch (device globals; no allocation) ----------------
__device__ float    g_dch[HWT];            // horizontal-min intermediate
__device__ float    g_dc[HWT];             // dark channel
__device__ float    g_vsum[10*HWT];        // 10 vertically box-summed planes (160MB)
__device__ unsigned g_hist1[2048];         // coarse bins: float bits >> 19
__device__ unsigned g_hist2b[524288];      // fine bins: low 19 bits (within coarse bin)
__device__ unsigned g_chunk[1024];         // 512-bin chunk sums of g_hist2b
__device__ unsigned g_selKey;
__device__ unsigned g_selRank;
__device__ float    g_thres;
__device__ unsigned g_cnt;
__device__ float    g_sumr, g_sumg, g_sumb;
__device__ float    g_avg, g_invavg;

// ---------------- init: zero histograms / accumulators ----------------
__global__ void k_init() {
    int i = blockIdx.x * blockDim.x + threadIdx.x;
    if (i < 524288) g_hist2b[i] = 0u;
    if (i < 2048)   g_hist1[i]  = 0u;
    if (i < 1024)   g_chunk[i]  = 0u;
    if (i == 0) {
        g_cnt = 0u; g_sumr = 0.f; g_sumg = 0.f; g_sumb = 0.f;
        g_selKey = 0u; g_selRank = 0u; g_thres = 0.f;
    }
}

// ---------------- channel-min + horizontal min (r=7) ----------------
__global__ void __launch_bounds__(256) k_cmin_hmin(const float* __restrict__ x) {
    __shared__ float s[256 + 2*RD];
    int row = blockIdx.y;
    int x0  = blockIdx.x * 256;
    int t   = threadIdx.x;
    for (int i = t; i < 256 + 2*RD; i += 256) {
        int xx = x0 - RD + i;
        float v = 1e30f;
        if (xx >= 0 && xx < WW) {
            float r = x[0*HWT + row*WW + xx];
            float g = x[1*HWT + row*WW + xx];
            float b = x[2*HWT + row*WW + xx];
            v = fminf(r, fminf(g, b));
        }
        s[i] = v;
    }
    __syncthreads();
    float m = s[t];
#pragma unroll
    for (int j = 1; j <= 2*RD; j++) m = fminf(m, s[t + j]);
    g_dch[row*WW + x0 + t] = m;
}

// ---------------- vertical min (r=7) + fused coarse histogram ----------------
__global__ void __launch_bounds__(256) k_vmin_hist() {
    __shared__ float s[16 + 2*RD][256];
    __shared__ unsigned sh[2048];
    int t = threadIdx.x;
    for (int i = t; i < 2048; i += 256) sh[i] = 0u;
    int xx = blockIdx.x * 256 + t;
    int y0 = blockIdx.y * 16;
    for (int r = 0; r < 16 + 2*RD; r++) {
        int yy = y0 - RD + r;
        s[r][t] = (yy >= 0 && yy < HH) ? g_dch[yy*WW + xx] : 1e30f;
    }
    __syncthreads();
    int lane = t & 31;
    for (int k = 0; k < 16; k++) {
        float m = s[k][t];
#pragma unroll
        for (int j = 1; j <= 2*RD; j++) m = fminf(m, s[k + j][t]);
        g_dc[(y0 + k)*WW + xx] = m;
        unsigned key = __float_as_uint(m) >> 19;   // < 2048 for dc in [0,1)
        unsigned prev = __shfl_up_sync(0xffffffffu, key, 1);
        bool leader = (lane == 0) || (key != prev);
        unsigned bal = __ballot_sync(0xffffffffu, leader);
        if (leader) {
            unsigned above = (lane == 31) ? 0u : (bal >> (lane + 1));
            int run = above ? __ffs((int)above) : (32 - lane);
            atomicAdd(&sh[key], (unsigned)run);
        }
    }
    __syncthreads();
    for (int i = t; i < 2048; i += 256) {
        unsigned v = sh[i];
        if (v) atomicAdd(&g_hist1[i], v);
    }
}

// ---------------- find coarse bin containing the KSEL-th largest ----------------
__global__ void __launch_bounds__(256) k_scan1() {
    __shared__ unsigned part[256];
    int t = threadIdx.x;
    int hi = 2047 - 8 * t;
    unsigned sum = 0;
#pragma unroll
    for (int j = 0; j < 8; j++) sum += g_hist1[hi - j];
    part[t] = sum;
    __syncthreads();
    if (t == 0) {
        unsigned cum = 0; int sel = 0;
        for (int i = 0; i < 256; i++) {
            if (cum + part[i] >= KSEL) { sel = i; break; }
            cum += part[i];
        }
        int hb = 2047 - 8 * sel;
        for (int j = 0; j < 8; j++) {
            unsigned h = g_hist1[hb - j];
            if (cum + h >= KSEL) {
                g_selKey = (unsigned)(hb - j);
                g_selRank = KSEL - cum;
                break;
            }
            cum += h;
        }
    }
}

// ---------------- histogram pass 2: low 19 bits within selected bin (uint4) ----------------
__global__ void k_hist2() {
    unsigned B = g_selKey;
    const uint4* __restrict__ dc4 = reinterpret_cast<const uint4*>(g_dc);
    int tid = blockIdx.x * blockDim.x + threadIdx.x;
    int stride = gridDim.x * blockDim.x;
    for (int i = tid; i < HWT/4; i += stride) {
        uint4 v = dc4[i];
        if ((v.x >> 19) == B) atomicAdd(&g_hist2b[v.x & 0x7FFFFu], 1u);
        if ((v.y >> 19) == B) atomicAdd(&g_hist2b[v.y & 0x7FFFFu], 1u);
        if ((v.z >> 19) == B) atomicAdd(&g_hist2b[v.z & 0x7FFFFu], 1u);
        if ((v.w >> 19) == B) atomicAdd(&g_hist2b[v.w & 0x7FFFFu], 1u);
    }
}

// ---------------- reduce fine histogram into 1024 chunk sums (coalesced) ----------------
__global__ void __launch_bounds__(128) k_chunks() {
    __shared__ unsigned w[4];
    int b = blockIdx.x, t = threadIdx.x;
    unsigned s = 0;
#pragma unroll
    for (int k = 0; k < 4; k++) s += g_hist2b[b * 512 + k * 128 + t];
#pragma unroll
    for (int o = 16; o > 0; o >>= 1) s += __shfl_down_sync(0xffffffffu, s, o);
    if ((t & 31) == 0) w[t >> 5] = s;
    __syncthreads();
    if (t == 0) g_chunk[b] = w[0] + w[1] + w[2] + w[3];
}

// ---------------- select chunk, then exact fine bin ----------------
__global__ void __launch_bounds__(1024) k_scan2() {
    __shared__ unsigned sc[1024];
    __shared__ unsigned sb[512];
    __shared__ int selC;
    __shared__ unsigned selR;
    unsigned K = g_selRank;
    int t = threadIdx.x;
    sc[t] = g_chunk[t];                     // coalesced
    __syncthreads();
    if (t == 0) {
        unsigned cum = 0;
        for (int j = 1023; j >= 0; j--) {
            unsigned h = sc[j];
            if (cum + h >= K) { selC = j; selR = K - cum; break; }
            cum += h;
        }
    }
    __syncthreads();
    int c = selC;
    if (t < 512) sb[t] = g_hist2b[c * 512 + t];   // coalesced
    __syncthreads();
    if (t == 0) {
        unsigned K2 = selR;
        unsigned cum = 0;
        for (int j = 511; j >= 0; j--) {
            unsigned h = sb[j];
            if (cum + h >= K2) {
                g_thres = __uint_as_float((g_selKey << 19) | (unsigned)(c * 512 + j));
                break;
            }
            cum += h;
        }
    }
}

// ---------------- masked sums for atmospheric light (float4 dc) ----------------
__global__ void k_mask(const float* __restrict__ x) {
    float th = g_thres;
    const float4* __restrict__ dc4 = reinterpret_cast<const float4*>(g_dc);
    int tid = blockIdx.x * blockDim.x + threadIdx.x;
    int stride = gridDim.x * blockDim.x;
    unsigned cnt = 0; float sr = 0.f, sg = 0.f, sb = 0.f;
    for (int i = tid; i < HWT/4; i += stride) {
        float4 d = dc4[i];
        int base = i * 4;
#pragma unroll
        for (int j = 0; j < 4; j++) {
            float dv = (j == 0) ? d.x : (j == 1) ? d.y : (j == 2) ? d.z : d.w;
            if (dv >= th) {
                cnt++;
                sr += x[base + j];
                sg += x[HWT + base + j];
                sb += x[2*HWT + base + j];
            }
        }
    }
#pragma unroll
    for (int o = 16; o > 0; o >>= 1) {
        cnt += __shfl_down_sync(0xffffffffu, cnt, o);
        sr  += __shfl_down_sync(0xffffffffu, sr,  o);
        sg  += __shfl_down_sync(0xffffffffu, sg,  o);
        sb  += __shfl_down_sync(0xffffffffu, sb,  o);
    }
    if ((threadIdx.x & 31) == 0) {
        atomicAdd(&g_cnt, cnt);
        atomicAdd(&g_sumr, sr);
        atomicAdd(&g_sumg, sg);
        atomicAdd(&g_sumb, sb);
    }
}

__global__ void k_avg() {
    float c = (float)g_cnt;
    float avg = (0.299f * g_sumr + 0.587f * g_sumg + 0.114f * g_sumb) / c;
    g_avg = avg;
    g_invavg = 1.0f / avg;
}

// ---------------- helpers for the vertical pass (float2) ----------------
__device__ __forceinline__ void vload2(const float* __restrict__ x, int yy, int c,
                                       float2 r[4]) {
    int o = yy * WW + c;
    r[0] = *(const float2*)(x + o);
    r[1] = *(const float2*)(x + HWT + o);
    r[2] = *(const float2*)(x + 2*HWT + o);
    r[3] = *(const float2*)(g_dc + o);
}

__device__ __forceinline__ void vplanes2(const float2 r[4], float inva, float2 v[10]) {
    float px = fmaf(-OMEGA * inva, r[3].x, 1.0f);
    float py = fmaf(-OMEGA * inva, r[3].y, 1.0f);
    v[0] = make_float2(px, py);
    v[1] = r[0]; v[2] = r[1]; v[3] = r[2];
    v[4] = make_float2(px * r[0].x, py * r[0].y);
    v[5] = make_float2(px * r[1].x, py * r[1].y);
    v[6] = make_float2(px * r[2].x, py * r[2].y);
    v[7] = make_float2(r[0].x * r[0].x, r[0].y * r[0].y);
    v[8] = make_float2(r[1].x * r[1].x, r[1].y * r[1].y);
    v[9] = make_float2(r[2].x * r[2].x, r[2].y * r[2].y);
}

// ---------------- vertical rolling box sums of the 10 planes (float2) ----------------
#define VS 16
__global__ void __launch_bounds__(256) k_vpass(const float* __restrict__ x) {
    int c  = (blockIdx.x * 256 + threadIdx.x) * 2;
    int y0 = blockIdx.y * VS;
    float inva = g_invavg;
    float2 s[10];
#pragma unroll
    for (int p = 0; p < 10; p++) s[p] = make_float2(0.f, 0.f);

    bool interior = (y0 >= RG + 1) && (y0 + VS - 1 + RG < HH);

    int ylo = y0 - RG; if (ylo < 0) ylo = 0;
    int yhi = y0 + RG; if (yhi > HH - 1) yhi = HH - 1;
#pragma unroll 4
    for (int yy = ylo; yy <= yhi; yy++) {
        float2 r[4]; vload2(x, yy, c, r);
        float2 v[10]; vplanes2(r, inva, v);
#pragma unroll
        for (int p = 0; p < 10; p++) { s[p].x += v[p].x; s[p].y += v[p].y; }
    }

    if (interior) {
        float2 ra[4], rs[4];
        vload2(x, y0 + 1 + RG, c, ra);
        vload2(x, y0 - RG, c, rs);
#pragma unroll
        for (int p = 0; p < 10; p++)
            *(float2*)(g_vsum + p*HWT + y0*WW + c) = s[p];
        for (int k = 1; k < VS; k++) {
            int y = y0 + k;
            float2 vA[10], vS[10];
            vplanes2(ra, inva, vA);
            vplanes2(rs, inva, vS);
#pragma unroll
            for (int p = 0; p < 10; p++) {
                s[p].x += vA[p].x - vS[p].x;
                s[p].y += vA[p].y - vS[p].y;
            }
            if (k + 1 < VS) {
                vload2(x, y + 1 + RG, c, ra);
                vload2(x, y - RG, c, rs);
            }
#pragma unroll
            for (int p = 0; p < 10; p++)
                *(float2*)(g_vsum + p*HWT + y*WW + c) = s[p];
        }
    } else {
        for (int k = 0; k < VS; k++) {
            int y = y0 + k;
            if (k > 0) {
                int ya = y + RG;
                if (ya < HH) {
                    float2 r[4]; vload2(x, ya, c, r);
                    float2 v[10]; vplanes2(r, inva, v);
#pragma unroll
                    for (int p = 0; p < 10; p++) { s[p].x += v[p].x; s[p].y += v[p].y; }
                }
                int yr = y - RG - 1;
                if (yr >= 0) {
                    float2 r[4]; vload2(x, yr, c, r);
                    float2 v[10]; vplanes2(r, inva, v);
#pragma unroll
                    for (int p = 0; p < 10; p++) { s[p].x -= v[p].x; s[p].y -= v[p].y; }
                }
            }
#pragma unroll
            for (int p = 0; p < 10; p++)
                *(float2*)(g_vsum + p*HWT + y*WW + c) = s[p];
        }
    }
}

// ---------------- horizontal pass: bulk load + warp-local scans + epilogue ----------------
// one block per half-row: 1024 outputs, segment 1144 padded to 1152 (36 warps)
#define SEG 1144
#define SEGP 1152
__global__ void __launch_bounds__(256) k_hfinal(const float* __restrict__ x,
                                                float* __restrict__ out) {
    __shared__ float sps[10*SEGP];       // warp-local inclusive scans (in place)
    __shared__ float swt[10*36];         // warp totals
    int row = blockIdx.y;
    int c0  = blockIdx.x * 1024;
    int s0  = c0 - RG;
    int t = threadIdx.x, lane = t & 31, w = t >> 5;

    // phase 1: bulk load 10 planes x SEGP (zero-padded) — 45 independent loads/thread
    const float* __restrict__ vs = g_vsum + row * WW;
#pragma unroll
    for (int i = 0; i < 45; i++) {
        int idx = i * 256 + t;           // < 11520
        int pl  = idx / SEGP;
        int L   = idx - pl * SEGP;
        int gc  = s0 + L;
        float v = 0.f;
        if (L < SEG && gc >= 0 && gc < WW) v = vs[pl * HWT + gc];
        sps[idx] = v;
    }
    __syncthreads();

    // phase 2: 360 independent warp-local inclusive scans (no cross-warp carries)
    // warp w handles segments w, w+8, ... (45 per warp)
#pragma unroll
    for (int i = 0; i < 45; i++) {
        int seg = i * 8 + w;             // < 360
        int idx = seg * 32 + lane;
        float v = sps[idx];
#pragma unroll
        for (int o = 1; o < 32; o <<= 1) {
            float n = __shfl_up_sync(0xffffffffu, v, o);
            if (lane >= o) v += n;
        }
        sps[idx] = v;
        if (lane == 31) swt[seg] = v;    // swt[pl*36 + local_seg], since SEGP/32=36
    }
    __syncthreads();

    // phase 3: windowed diff via warp-local scans + totals, then epilogue
    float avg = g_avg;
    int ny = min(row + RG, HH - 1) - max(row - RG, 0) + 1;
#pragma unroll
    for (int j = 0; j < 4; j++) {
        int L = t + j * 256;             // 0..1023
        int gc = c0 + L;
        int hi = L + 2*RG;               // in [120, 1143]
        int lo = L - 1;                  // in [-1, 1022]
        int jhi = hi >> 5, jlo = (lo >= 0) ? (lo >> 5) : -1;
        float wv[10];
#pragma unroll
        for (int p = 0; p < 10; p++) {
            float sum = sps[p*SEGP + hi];
            if (lo >= 0) {
                if (jlo == jhi) sum -= sps[p*SEGP + lo];
                else {
                    sum -= sps[p*SEGP + lo];
                    for (int q = jlo; q < jhi; q++) sum += swt[p*36 + q];
                }
            } else {
                for (int q = 0; q < jhi; q++) sum += swt[p*36 + q];
            }
            wv[p] = sum;
        }
        int nx = min(gc + RG, WW - 1) - max(gc - RG, 0) + 1;
        float invN = __fdividef(1.0f, (float)(nx * ny));
        float mp = wv[0] * invN;
        int base = row * WW + gc;
#pragma unroll
        for (int ch = 0; ch < 3; ch++) {
            float mi  = wv[1 + ch] * invN;
            float mpi = wv[4 + ch] * invN;
            float mii = wv[7 + ch] * invN;
            float cip = mpi - mp * mi;
            float cii = mii - mi * mi;
            float a = __fdividef(cip, cii + EPSG);
            float b = mp - a * mi;
            float xi = x[ch * HWT + base];
            float rt = fminf(fmaxf(a * xi + b, 0.0f), 1.0f);
            rt = fmaxf(rt, 0.1f);
            float yv = __fdividef(xi - avg, rt) + avg;
            out[ch * HWT + base] = fminf(fmaxf(yv, 0.0f), 1.0f);
        }
    }
}

// ---------------- launch ----------------
extern "C" void kernel_launch(void* const* d_in, const int* in_sizes, int n_in,
                              void* d_out, int out_size) {
    const float* x = (const float*)d_in[0];
    float* out = (float*)d_out;

    k_init<<<2048, 256>>>();
    k_cmin_hmin<<<dim3(8, 2048), 256>>>(x);
    k_vmin_hist<<<dim3(8, 128), 256>>>();
    k_scan1<<<1, 256>>>();
    k_hist2<<<1024, 256>>>();
    k_chunks<<<1024, 128>>>();
    k_scan2<<<1, 1024>>>();
    k_mask<<<1024, 256>>>(x);
    k_avg<<<1, 1>>>();
    k_vpass<<<dim3(4, 128), 256>>>(x);
    k_hfinal<<<dim3(2, 2048), 256>>>(x, out);
}

// round 15
// speedup vs baseline: 1.0498x; 1.0480x over previous
#include <cuda_runtime.h>

#define HH 2048
#define WW 2048
#define HWT (HH*WW)
#define RD 7
#define RG 60
#define KSEL 4195u          /* (H*W)//1000 + 1 : rank of threshold (1-based from top) */
#define OMEGA 0.95f
#define EPSG 1e-4f

// ---------------- scratch (device globals; no allocation) ----------------
__device__ float    g_dch[HWT];            // horizontal-min intermediate
__device__ float    g_dc[HWT];             // dark channel
__device__ float    g_vsum[10*HWT];        // 10 vertically box-summed planes (160MB)
__device__ unsigned g_hist1[2048];         // coarse bins: float bits >> 19
__device__ unsigned g_hist2b[524288];      // fine bins: low 19 bits (within coarse bin)
__device__ unsigned g_chunk[1024];         // 512-bin chunk sums of g_hist2b
__device__ unsigned g_selKey;
__device__ unsigned g_selRank;
__device__ float    g_thres;
__device__ unsigned g_cnt;
__device__ float    g_sumr, g_sumg, g_sumb;
__device__ float    g_avg, g_invavg;

// ---------------- init: zero histograms / accumulators ----------------
__global__ void k_init() {
    int i = blockIdx.x * blockDim.x + threadIdx.x;
    if (i < 524288) g_hist2b[i] = 0u;
    if (i < 2048)   g_hist1[i]  = 0u;
    if (i < 1024)   g_chunk[i]  = 0u;
    if (i == 0) {
        g_cnt = 0u; g_sumr = 0.f; g_sumg = 0.f; g_sumb = 0.f;
        g_selKey = 0u; g_selRank = 0u; g_thres = 0.f;
    }
}

// ---------------- channel-min + horizontal min (r=7) ----------------
__global__ void __launch_bounds__(256) k_cmin_hmin(const float* __restrict__ x) {
    __shared__ float s[256 + 2*RD];
    int row = blockIdx.y;
    int x0  = blockIdx.x * 256;
    int t   = threadIdx.x;
    for (int i = t; i < 256 + 2*RD; i += 256) {
        int xx = x0 - RD + i;
        float v = 1e30f;
        if (xx >= 0 && xx < WW) {
            float r = x[0*HWT + row*WW + xx];
            float g = x[1*HWT + row*WW + xx];
            float b = x[2*HWT + row*WW + xx];
            v = fminf(r, fminf(g, b));
        }
        s[i] = v;
    }
    __syncthreads();
    float m = s[t];
#pragma unroll
    for (int j = 1; j <= 2*RD; j++) m = fminf(m, s[t + j]);
    g_dch[row*WW + x0 + t] = m;
}

// ---------------- vertical min (r=7) + fused coarse histogram ----------------
__global__ void __launch_bounds__(256) k_vmin_hist() {
    __shared__ float s[16 + 2*RD][256];
    __shared__ unsigned sh[2048];
    int t = threadIdx.x;
    for (int i = t; i < 2048; i += 256) sh[i] = 0u;
    int xx = blockIdx.x * 256 + t;
    int y0 = blockIdx.y * 16;
    for (int r = 0; r < 16 + 2*RD; r++) {
        int yy = y0 - RD + r;
        s[r][t] = (yy >= 0 && yy < HH) ? g_dch[yy*WW + xx] : 1e30f;
    }
    __syncthreads();
    int lane = t & 31;
    for (int k = 0; k < 16; k++) {
        float m = s[k][t];
#pragma unroll
        for (int j = 1; j <= 2*RD; j++) m = fminf(m, s[k + j][t]);
        g_dc[(y0 + k)*WW + xx] = m;
        unsigned key = __float_as_uint(m) >> 19;   // < 2048 for dc in [0,1)
        unsigned prev = __shfl_up_sync(0xffffffffu, key, 1);
        bool leader = (lane == 0) || (key != prev);
        unsigned bal = __ballot_sync(0xffffffffu, leader);
        if (leader) {
            unsigned above = (lane == 31) ? 0u : (bal >> (lane + 1));
            int run = above ? __ffs((int)above) : (32 - lane);
            atomicAdd(&sh[key], (unsigned)run);
        }
    }
    __syncthreads();
    for (int i = t; i < 2048; i += 256) {
        unsigned v = sh[i];
        if (v) atomicAdd(&g_hist1[i], v);
    }
}

// ---------------- helpers for the vertical pass (dc-based planes, no avg dep) ----------------
__device__ __forceinline__ void vload(const float* __restrict__ x, int yy, int c,
                                      float r[4]) {
    int o = yy * WW + c;
    r[0] = x[o]; r[1] = x[HWT + o]; r[2] = x[2*HWT + o]; r[3] = g_dc[o];
}

__device__ __forceinline__ void vplanes(const float r[4], float v[10]) {
    float d = r[3];
    v[0] = d;
    v[1] = r[0]; v[2] = r[1]; v[3] = r[2];
    v[4] = d * r[0]; v[5] = d * r[1]; v[6] = d * r[2];
    v[7] = r[0] * r[0]; v[8] = r[1] * r[1]; v[9] = r[2] * r[2];
}

// ---------------- vertical rolling box sums of the 10 planes ----------------
#define VS 32
__global__ void __launch_bounds__(256) k_vpass(const float* __restrict__ x) {
    int c  = blockIdx.x * 256 + threadIdx.x;
    int y0 = blockIdx.y * VS;
    float s[10];
#pragma unroll
    for (int p = 0; p < 10; p++) s[p] = 0.f;

    bool interior = (y0 >= RG + 1) && (y0 + VS - 1 + RG < HH);

    int ylo = y0 - RG; if (ylo < 0) ylo = 0;
    int yhi = y0 + RG; if (yhi > HH - 1) yhi = HH - 1;
#pragma unroll 4
    for (int yy = ylo; yy <= yhi; yy++) {
        float r[4]; vload(x, yy, c, r);
        float v[10]; vplanes(r, v);
#pragma unroll
        for (int p = 0; p < 10; p++) s[p] += v[p];
    }

    if (interior) {
        float ra[4], rs[4];
        vload(x, y0 + 1 + RG, c, ra);
        vload(x, y0 - RG, c, rs);
#pragma unroll
        for (int p = 0; p < 10; p++)
            g_vsum[p*HWT + y0*WW + c] = s[p];
        for (int k = 1; k < VS; k++) {
            int y = y0 + k;
            float vA[10], vS[10];
            vplanes(ra, vA);
            vplanes(rs, vS);
#pragma unroll
            for (int p = 0; p < 10; p++) s[p] += vA[p] - vS[p];
            if (k + 1 < VS) {
                vload(x, y + 1 + RG, c, ra);
                vload(x, y - RG, c, rs);
            }
#pragma unroll
            for (int p = 0; p < 10; p++)
                g_vsum[p*HWT + y*WW + c] = s[p];
        }
    } else {
        for (int k = 0; k < VS; k++) {
            int y = y0 + k;
            if (k > 0) {
                int ya = y + RG;
                if (ya < HH) {
                    float r[4]; vload(x, ya, c, r);
                    float v[10]; vplanes(r, v);
#pragma unroll
                    for (int p = 0; p < 10; p++) s[p] += v[p];
                }
                int yr = y - RG - 1;
                if (yr >= 0) {
                    float r[4]; vload(x, yr, c, r);
                    float v[10]; vplanes(r, v);
#pragma unroll
                    for (int p = 0; p < 10; p++) s[p] -= v[p];
                }
            }
#pragma unroll
            for (int p = 0; p < 10; p++)
                g_vsum[p*HWT + y*WW + c] = s[p];
        }
    }
}

// ---------------- find coarse bin containing the KSEL-th largest ----------------
__global__ void __launch_bounds__(256) k_scan1() {
    __shared__ unsigned part[256];
    int t = threadIdx.x;
    int hi = 2047 - 8 * t;
    unsigned sum = 0;
#pragma unroll
    for (int j = 0; j < 8; j++) sum += g_hist1[hi - j];
    part[t] = sum;
    __syncthreads();
    if (t == 0) {
        unsigned cum = 0; int sel = 0;
        for (int i = 0; i < 256; i++) {
            if (cum + part[i] >= KSEL) { sel = i; break; }
            cum += part[i];
        }
        int hb = 2047 - 8 * sel;
        for (int j = 0; j < 8; j++) {
            unsigned h = g_hist1[hb - j];
            if (cum + h >= KSEL) {
                g_selKey = (unsigned)(hb - j);
                g_selRank = KSEL - cum;
                break;
            }
            cum += h;
        }
    }
}

// ---------------- histogram pass 2: low 19 bits within selected bin (uint4) ----------------
__global__ void k_hist2() {
    unsigned B = g_selKey;
    const uint4* __restrict__ dc4 = reinterpret_cast<const uint4*>(g_dc);
    int tid = blockIdx.x * blockDim.x + threadIdx.x;
    int stride = gridDim.x * blockDim.x;
    for (int i = tid; i < HWT/4; i += stride) {
        uint4 v = dc4[i];
        if ((v.x >> 19) == B) atomicAdd(&g_hist2b[v.x & 0x7FFFFu], 1u);
        if ((v.y >> 19) == B) atomicAdd(&g_hist2b[v.y & 0x7FFFFu], 1u);
        if ((v.z >> 19) == B) atomicAdd(&g_hist2b[v.z & 0x7FFFFu], 1u);
        if ((v.w >> 19) == B) atomicAdd(&g_hist2b[v.w & 0x7FFFFu], 1u);
    }
}

// ---------------- reduce fine histogram into 1024 chunk sums (coalesced) ----------------
__global__ void __launch_bounds__(128) k_chunks() {
    __shared__ unsigned w[4];
    int b = blockIdx.x, t = threadIdx.x;
    unsigned s = 0;
#pragma unroll
    for (int k = 0; k < 4; k++) s += g_hist2b[b * 512 + k * 128 + t];
#pragma unroll
    for (int o = 16; o > 0; o >>= 1) s += __shfl_down_sync(0xffffffffu, s, o);
    if ((t & 31) == 0) w[t >> 5] = s;
    __syncthreads();
    if (t == 0) g_chunk[b] = w[0] + w[1] + w[2] + w[3];
}

// ---------------- select chunk, then exact fine bin ----------------
__global__ void __launch_bounds__(1024) k_scan2() {
    __shared__ unsigned sc[1024];
    __shared__ unsigned sb[512];
    __shared__ int selC;
    __shared__ unsigned selR;
    unsigned K = g_selRank;
    int t = threadIdx.x;
    sc[t] = g_chunk[t];                     // coalesced
    __syncthreads();
    if (t == 0) {
        unsigned cum = 0;
        for (int j = 1023; j >= 0; j--) {
            unsigned h = sc[j];
            if (cum + h >= K) { selC = j; selR = K - cum; break; }
            cum += h;
        }
    }
    __syncthreads();
    int c = selC;
    if (t < 512) sb[t] = g_hist2b[c * 512 + t];   // coalesced
    __syncthreads();
    if (t == 0) {
        unsigned K2 = selR;
        unsigned cum = 0;
        for (int j = 511; j >= 0; j--) {
            unsigned h = sb[j];
            if (cum + h >= K2) {
                g_thres = __uint_as_float((g_selKey << 19) | (unsigned)(c * 512 + j));
                break;
            }
            cum += h;
        }
    }
}

// ---------------- masked sums for atmospheric light (float4 dc) ----------------
__global__ void k_mask(const float* __restrict__ x) {
    float th = g_thres;
    const float4* __restrict__ dc4 = reinterpret_cast<const float4*>(g_dc);
    int tid = blockIdx.x * blockDim.x + threadIdx.x;
    int stride = gridDim.x * blockDim.x;
    unsigned cnt = 0; float sr = 0.f, sg = 0.f, sb = 0.f;
    for (int i = tid; i < HWT/4; i += stride) {
        float4 d = dc4[i];
        int base = i * 4;
#pragma unroll
        for (int j = 0; j < 4; j++) {
            float dv = (j == 0) ? d.x : (j == 1) ? d.y : (j == 2) ? d.z : d.w;
            if (dv >= th) {
                cnt++;
                sr += x[base + j];
                sg += x[HWT + base + j];
                sb += x[2*HWT + base + j];
            }
        }
    }
#pragma unroll
    for (int o = 16; o > 0; o >>= 1) {
        cnt += __shfl_down_sync(0xffffffffu, cnt, o);
        sr  += __shfl_down_sync(0xffffffffu, sr,  o);
        sg  += __shfl_down_sync(0xffffffffu, sg,  o);
        sb  += __shfl_down_sync(0xffffffffu, sb,  o);
    }
    if ((threadIdx.x & 31) == 0) {
        atomicAdd(&g_cnt, cnt);
        atomicAdd(&g_sumr, sr);
        atomicAdd(&g_sumg, sg);
        atomicAdd(&g_sumb, sb);
    }
}

__global__ void k_avg() {
    float c = (float)g_cnt;
    float avg = (0.299f * g_sumr + 0.587f * g_sumg + 0.114f * g_sumb) / c;
    g_avg = avg;
    g_invavg = 1.0f / avg;
}

// ---------------- horizontal box sums (block scans, 2 planes/round) + epilogue ----------------
// one block per half-row: 1024 output cols + 60-col halo each side, zero-padded
// planes are dc-based; p-planes recovered affinely: mean_p = 1 - kap*mean_dc,
// mean_pi = mean_i - kap*mean_dci  (kap = OMEGA / avg)
#define SEG 1144
__global__ void __launch_bounds__(256) k_hfinal(const float* __restrict__ x,
                                                float* __restrict__ out) {
    __shared__ float sps[10][SEG];
    __shared__ float2 wpart[8];
    int row = blockIdx.y;
    int c0  = blockIdx.x * 1024;
    int s0  = c0 - RG;
    int t = threadIdx.x, lane = t & 31, wid = t >> 5;

    for (int pl = 0; pl < 10; pl += 2) {
        const float* __restrict__ srcA = g_vsum + (pl+0)*HWT + row*WW;
        const float* __restrict__ srcB = g_vsum + (pl+1)*HWT + row*WW;
        float carryA = 0.f, carryB = 0.f;
        for (int ch = 0; ch < 5; ch++) {
            int L = ch * 256 + t;
            int gc = s0 + L;
            float vA = 0.f, vB = 0.f;
            bool in = (L < SEG && gc >= 0 && gc < WW);
            if (in) { vA = srcA[gc]; vB = srcB[gc]; }
            float scA = vA, scB = vB;
#pragma unroll
            for (int o = 1; o < 32; o <<= 1) {
                float nA = __shfl_up_sync(0xffffffffu, scA, o);
                float nB = __shfl_up_sync(0xffffffffu, scB, o);
                if (lane >= o) { scA += nA; scB += nB; }
            }
            if (lane == 31) wpart[wid] = make_float2(scA, scB);
            __syncthreads();
            float offA = carryA, offB = carryB, totA = 0.f, totB = 0.f;
#pragma unroll
            for (int w = 0; w < 8; w++) {
                float2 pw = wpart[w];
                totA += pw.x; totB += pw.y;
                if (w < wid) { offA += pw.x; offB += pw.y; }
            }
            if (L < SEG) {
                sps[pl+0][L] = scA + offA;
                sps[pl+1][L] = scB + offB;
            }
            carryA += totA; carryB += totB;
            __syncthreads();
        }
    }

    float avg = g_avg;
    float kap = OMEGA * g_invavg;
    int ny = min(row + RG, HH - 1) - max(row - RG, 0) + 1;
#pragma unroll
    for (int j = 0; j < 4; j++) {
        int L = t + j * 256;          // 0..1023
        int gc = c0 + L;
        int hi = L + 2*RG;            // local index of gc+RG
        int lo = L - 1;               // local index of gc-RG-1
        float w0 = sps[0][hi] - (lo >= 0 ? sps[0][lo] : 0.f);
        float w1 = sps[1][hi] - (lo >= 0 ? sps[1][lo] : 0.f);
        float w2 = sps[2][hi] - (lo >= 0 ? sps[2][lo] : 0.f);
        float w3 = sps[3][hi] - (lo >= 0 ? sps[3][lo] : 0.f);
        float w4 = sps[4][hi] - (lo >= 0 ? sps[4][lo] : 0.f);
        float w5 = sps[5][hi] - (lo >= 0 ? sps[5][lo] : 0.f);
        float w6 = sps[6][hi] - (lo >= 0 ? sps[6][lo] : 0.f);
        float w7 = sps[7][hi] - (lo >= 0 ? sps[7][lo] : 0.f);
        float w8 = sps[8][hi] - (lo >= 0 ? sps[8][lo] : 0.f);
        float w9 = sps[9][hi] - (lo >= 0 ? sps[9][lo] : 0.f);
        int nx = min(gc + RG, WW - 1) - max(gc - RG, 0) + 1;
        float invN = __fdividef(1.0f, (float)(nx * ny));
        float mdc = w0 * invN;
        float mp  = 1.0f - kap * mdc;          // mean of p
        float mi, mdci, mpi, mii, cip, cii, a, b, xi, rt, yv;
        // ch 0
        mi = w1 * invN; mdci = w4 * invN; mii = w7 * invN;
        mpi = mi - kap * mdci;
        cip = mpi - mp * mi; cii = mii - mi * mi;
        a = __fdividef(cip, cii + EPSG); b = mp - a * mi;
        xi = x[0*HWT + row*WW + gc];
        rt = fminf(fmaxf(a * xi + b, 0.0f), 1.0f); rt = fmaxf(rt, 0.1f);
        yv = __fdividef(xi - avg, rt) + avg;
        out[0*HWT + row*WW + gc] = fminf(fmaxf(yv, 0.0f), 1.0f);
        // ch 1
        mi = w2 * invN; mdci = w5 * invN; mii = w8 * invN;
        mpi = mi - kap * mdci;
        cip = mpi - mp * mi; cii = mii - mi * mi;
        a = __fdividef(cip, cii + EPSG); b = mp - a * mi;
        xi = x[1*HWT + row*WW + gc];
        rt = fminf(fmaxf(a * xi + b, 0.0f), 1.0f); rt = fmaxf(rt, 0.1f);
        yv = __fdividef(xi - avg, rt) + avg;
        out[1*HWT + row*WW + gc] = fminf(fmaxf(yv, 0.0f), 1.0f);
        // ch 2
        mi = w3 * invN; mdci = w6 * invN; mii = w9 * invN;
        mpi = mi - kap * mdci;
        cip = mpi - mp * mi; cii = mii - mi * mi;
        a = __fdividef(cip, cii + EPSG); b = mp - a * mi;
        xi = x[2*HWT + row*WW + gc];
        rt = fminf(fmaxf(a * xi + b, 0.0f), 1.0f); rt = fmaxf(rt, 0.1f);
        yv = __fdividef(xi - avg, rt) + avg;
        out[2*HWT + row*WW + gc] = fminf(fmaxf(yv, 0.0f), 1.0f);
    }
}

// ---------------- launch ----------------
extern "C" void kernel_launch(void* const* d_in, const int* in_sizes, int n_in,
                              void* d_out, int out_size) {
    const float* x = (const float*)d_in[0];
    float* out = (float*)d_out;

    k_init<<<2048, 256>>>();
    k_cmin_hmin<<<dim3(8, 2048), 256>>>(x);
    k_vmin_hist<<<dim3(8, 128), 256>>>();
    k_vpass<<<dim3(8, 64), 256>>>(x);      // launch #4 — lands in the ncu window
    k_scan1<<<1, 256>>>();
    k_hist2<<<1024, 256>>>();
    k_chunks<<<1024, 128>>>();
    k_scan2<<<1, 1024>>>();
    k_mask<<<1024, 256>>>(x);
    k_avg<<<1, 1>>>();
    k_hfinal<<<dim3(2, 2048), 256>>>(x, out);
}

// round 16
// speedup vs baseline: 1.2770x; 1.2164x over previous
#include <cuda_runtime.h>

#define HH 2048
#define WW 2048
#define HWT (HH*WW)
#define RD 7
#define RG 60
#define KSEL 4195u          /* (H*W)//1000 + 1 : rank of threshold (1-based from top) */
#define OMEGA 0.95f
#define EPSG 1e-4f

// ---------------- scratch (device globals; no allocation) ----------------
__device__ float    g_dch[HWT];            // horizontal-min intermediate
__device__ float    g_dc[HWT];             // dark channel
__device__ float    g_vsum[10*HWT];        // 10 vertically box-summed planes (160MB)
__device__ unsigned g_hist1[2048];         // coarse bins: float bits >> 19
__device__ unsigned g_hist2b[524288];      // fine bins: low 19 bits (within coarse bin)
__device__ unsigned g_chunk[1024];         // 512-bin chunk sums of g_hist2b
__device__ unsigned g_selKey;
__device__ unsigned g_selRank;
__device__ float    g_thres;
__device__ unsigned g_cnt;
__device__ float    g_sumr, g_sumg, g_sumb;
__device__ float    g_avg, g_invavg;

// ---------------- init: zero histograms / accumulators ----------------
__global__ void k_init() {
    int i = blockIdx.x * blockDim.x + threadIdx.x;
    if (i < 524288) g_hist2b[i] = 0u;
    if (i < 2048)   g_hist1[i]  = 0u;
    if (i < 1024)   g_chunk[i]  = 0u;
    if (i == 0) {
        g_cnt = 0u; g_sumr = 0.f; g_sumg = 0.f; g_sumb = 0.f;
        g_selKey = 0u; g_selRank = 0u; g_thres = 0.f;
    }
}

// ---------------- channel-min + horizontal min (r=7) ----------------
__global__ void __launch_bounds__(256) k_cmin_hmin(const float* __restrict__ x) {
    __shared__ float s[256 + 2*RD];
    int row = blockIdx.y;
    int x0  = blockIdx.x * 256;
    int t   = threadIdx.x;
    for (int i = t; i < 256 + 2*RD; i += 256) {
        int xx = x0 - RD + i;
        float v = 1e30f;
        if (xx >= 0 && xx < WW) {
            float r = x[0*HWT + row*WW + xx];
            float g = x[1*HWT + row*WW + xx];
            float b = x[2*HWT + row*WW + xx];
            v = fminf(r, fminf(g, b));
        }
        s[i] = v;
    }
    __syncthreads();
    float m = s[t];
#pragma unroll
    for (int j = 1; j <= 2*RD; j++) m = fminf(m, s[t + j]);
    g_dch[row*WW + x0 + t] = m;
}

// ---------------- vertical min (r=7) + fused coarse histogram ----------------
__global__ void __launch_bounds__(256) k_vmin_hist() {
    __shared__ float s[16 + 2*RD][256];
    __shared__ unsigned sh[2048];
    int t = threadIdx.x;
    for (int i = t; i < 2048; i += 256) sh[i] = 0u;
    int xx = blockIdx.x * 256 + t;
    int y0 = blockIdx.y * 16;
    for (int r = 0; r < 16 + 2*RD; r++) {
        int yy = y0 - RD + r;
        s[r][t] = (yy >= 0 && yy < HH) ? g_dch[yy*WW + xx] : 1e30f;
    }
    __syncthreads();
    int lane = t & 31;
    for (int k = 0; k < 16; k++) {
        float m = s[k][t];
#pragma unroll
        for (int j = 1; j <= 2*RD; j++) m = fminf(m, s[k + j][t]);
        g_dc[(y0 + k)*WW + xx] = m;
        unsigned key = __float_as_uint(m) >> 19;   // < 2048 for dc in [0,1)
        unsigned prev = __shfl_up_sync(0xffffffffu, key, 1);
        bool leader = (lane == 0) || (key != prev);
        unsigned bal = __ballot_sync(0xffffffffu, leader);
        if (leader) {
            unsigned above = (lane == 31) ? 0u : (bal >> (lane + 1));
            int run = above ? __ffs((int)above) : (32 - lane);
            atomicAdd(&sh[key], (unsigned)run);
        }
    }
    __syncthreads();
    for (int i = t; i < 2048; i += 256) {
        unsigned v = sh[i];
        if (v) atomicAdd(&g_hist1[i], v);
    }
}

// ---------------- helpers for the vertical pass (dc-based planes, no avg dep) ----------------
__device__ __forceinline__ void vload(const float* __restrict__ x, int yy, int c,
                                      float r[4]) {
    int o = yy * WW + c;
    r[0] = x[o]; r[1] = x[HWT + o]; r[2] = x[2*HWT + o]; r[3] = g_dc[o];
}

__device__ __forceinline__ void vplanes(const float r[4], float v[10]) {
    float d = r[3];
    v[0] = d;
    v[1] = r[0]; v[2] = r[1]; v[3] = r[2];
    v[4] = d * r[0]; v[5] = d * r[1]; v[6] = d * r[2];
    v[7] = r[0] * r[0]; v[8] = r[1] * r[1]; v[9] = r[2] * r[2];
}

// ---------------- vertical rolling box sums of the 10 planes ----------------
#define VS 32
__global__ void __launch_bounds__(256) k_vpass(const float* __restrict__ x) {
    int c  = blockIdx.x * 256 + threadIdx.x;
    int y0 = blockIdx.y * VS;
    float s[10];
#pragma unroll
    for (int p = 0; p < 10; p++) s[p] = 0.f;

    bool interior = (y0 >= RG + 1) && (y0 + VS - 1 + RG < HH);

    int ylo = y0 - RG; if (ylo < 0) ylo = 0;
    int yhi = y0 + RG; if (yhi > HH - 1) yhi = HH - 1;
#pragma unroll 4
    for (int yy = ylo; yy <= yhi; yy++) {
        float r[4]; vload(x, yy, c, r);
        float v[10]; vplanes(r, v);
#pragma unroll
        for (int p = 0; p < 10; p++) s[p] += v[p];
    }

    if (interior) {
        float ra[4], rs[4];
        vload(x, y0 + 1 + RG, c, ra);
        vload(x, y0 - RG, c, rs);
#pragma unroll
        for (int p = 0; p < 10; p++)
            g_vsum[p*HWT + y0*WW + c] = s[p];
        for (int k = 1; k < VS; k++) {
            int y = y0 + k;
            float vA[10], vS[10];
            vplanes(ra, vA);
            vplanes(rs, vS);
#pragma unroll
            for (int p = 0; p < 10; p++) s[p] += vA[p] - vS[p];
            if (k + 1 < VS) {
                vload(x, y + 1 + RG, c, ra);
                vload(x, y - RG, c, rs);
            }
#pragma unroll
            for (int p = 0; p < 10; p++)
                g_vsum[p*HWT + y*WW + c] = s[p];
        }
    } else {
        for (int k = 0; k < VS; k++) {
            int y = y0 + k;
            if (k > 0) {
                int ya = y + RG;
                if (ya < HH) {
                    float r[4]; vload(x, ya, c, r);
                    float v[10]; vplanes(r, v);
#pragma unroll
                    for (int p = 0; p < 10; p++) s[p] += v[p];
                }
                int yr = y - RG - 1;
                if (yr >= 0) {
                    float r[4]; vload(x, yr, c, r);
                    float v[10]; vplanes(r, v);
#pragma unroll
                    for (int p = 0; p < 10; p++) s[p] -= v[p];
                }
            }
#pragma unroll
            for (int p = 0; p < 10; p++)
                g_vsum[p*HWT + y*WW + c] = s[p];
        }
    }
}

// ---------------- find coarse bin containing the KSEL-th largest ----------------
__global__ void __launch_bounds__(256) k_scan1() {
    __shared__ unsigned part[256];
    int t = threadIdx.x;
    int hi = 2047 - 8 * t;
    unsigned sum = 0;
#pragma unroll
    for (int j = 0; j < 8; j++) sum += g_hist1[hi - j];
    part[t] = sum;
    __syncthreads();
    if (t == 0) {
        unsigned cum = 0; int sel = 0;
        for (int i = 0; i < 256; i++) {
            if (cum + part[i] >= KSEL) { sel = i; break; }
            cum += part[i];
        }
        int hb = 2047 - 8 * sel;
        for (int j = 0; j < 8; j++) {
            unsigned h = g_hist1[hb - j];
            if (cum + h >= KSEL) {
                g_selKey = (unsigned)(hb - j);
                g_selRank = KSEL - cum;
                break;
            }
            cum += h;
        }
    }
}

// ---------------- histogram pass 2: low 19 bits within selected bin (uint4) ----------------
__global__ void k_hist2() {
    unsigned B = g_selKey;
    const uint4* __restrict__ dc4 = reinterpret_cast<const uint4*>(g_dc);
    int tid = blockIdx.x * blockDim.x + threadIdx.x;
    int stride = gridDim.x * blockDim.x;
    for (int i = tid; i < HWT/4; i += stride) {
        uint4 v = dc4[i];
        if ((v.x >> 19) == B) atomicAdd(&g_hist2b[v.x & 0x7FFFFu], 1u);
        if ((v.y >> 19) == B) atomicAdd(&g_hist2b[v.y & 0x7FFFFu], 1u);
        if ((v.z >> 19) == B) atomicAdd(&g_hist2b[v.z & 0x7FFFFu], 1u);
        if ((v.w >> 19) == B) atomicAdd(&g_hist2b[v.w & 0x7FFFFu], 1u);
    }
}

// ---------------- reduce fine histogram into 1024 chunk sums (coalesced) ----------------
__global__ void __launch_bounds__(128) k_chunks() {
    __shared__ unsigned w[4];
    int b = blockIdx.x, t = threadIdx.x;
    unsigned s = 0;
#pragma unroll
    for (int k = 0; k < 4; k++) s += g_hist2b[b * 512 + k * 128 + t];
#pragma unroll
    for (int o = 16; o > 0; o >>= 1) s += __shfl_down_sync(0xffffffffu, s, o);
    if ((t & 31) == 0) w[t >> 5] = s;
    __syncthreads();
    if (t == 0) g_chunk[b] = w[0] + w[1] + w[2] + w[3];
}

// ---------------- select chunk, then exact fine bin ----------------
__global__ void __launch_bounds__(1024) k_scan2() {
    __shared__ unsigned sc[1024];
    __shared__ unsigned sb[512];
    __shared__ int selC;
    __shared__ unsigned selR;
    unsigned K = g_selRank;
    int t = threadIdx.x;
    sc[t] = g_chunk[t];                     // coalesced
    __syncthreads();
    if (t == 0) {
        unsigned cum = 0;
        for (int j = 1023; j >= 0; j--) {
            unsigned h = sc[j];
            if (cum + h >= K) { selC = j; selR = K - cum; break; }
            cum += h;
        }
    }
    __syncthreads();
    int c = selC;
    if (t < 512) sb[t] = g_hist2b[c * 512 + t];   // coalesced
    __syncthreads();
    if (t == 0) {
        unsigned K2 = selR;
        unsigned cum = 0;
        for (int j = 511; j >= 0; j--) {
            unsigned h = sb[j];
            if (cum + h >= K2) {
                g_thres = __uint_as_float((g_selKey << 19) | (unsigned)(c * 512 + j));
                break;
            }
            cum += h;
        }
    }
}

// ---------------- masked sums for atmospheric light (float4 dc) ----------------
__global__ void k_mask(const float* __restrict__ x) {
    float th = g_thres;
    const float4* __restrict__ dc4 = reinterpret_cast<const float4*>(g_dc);
    int tid = blockIdx.x * blockDim.x + threadIdx.x;
    int stride = gridDim.x * blockDim.x;
    unsigned cnt = 0; float sr = 0.f, sg = 0.f, sb = 0.f;
    for (int i = tid; i < HWT/4; i += stride) {
        float4 d = dc4[i];
        int base = i * 4;
#pragma unroll
        for (int j = 0; j < 4; j++) {
            float dv = (j == 0) ? d.x : (j == 1) ? d.y : (j == 2) ? d.z : d.w;
            if (dv >= th) {
                cnt++;
                sr += x[base + j];
                sg += x[HWT + base + j];
                sb += x[2*HWT + base + j];
            }
        }
    }
#pragma unroll
    for (int o = 16; o > 0; o >>= 1) {
        cnt += __shfl_down_sync(0xffffffffu, cnt, o);
        sr  += __shfl_down_sync(0xffffffffu, sr,  o);
        sg  += __shfl_down_sync(0xffffffffu, sg,  o);
        sb  += __shfl_down_sync(0xffffffffu, sb,  o);
    }
    if ((threadIdx.x & 31) == 0) {
        atomicAdd(&g_cnt, cnt);
        atomicAdd(&g_sumr, sr);
        atomicAdd(&g_sumg, sg);
        atomicAdd(&g_sumb, sb);
    }
}

__global__ void k_avg() {
    float c = (float)g_cnt;
    float avg = (0.299f * g_sumr + 0.587f * g_sumg + 0.114f * g_sumb) / c;
    g_avg = avg;
    g_invavg = 1.0f / avg;
}

// ---------------- horizontal pass: warp-local scans + exclusive warp-total prefix ----------------
// block = 512 outputs; segment 632 padded to 640 (20 warp-chunks per plane)
// window sum = (sps[hi] + E[jhi]) - (sps[lo] + E[jlo]),  E = exclusive prefix of warp totals
#define HB 512
#define HSEG 632
#define HSEGP 640
#define NSEGS 20
__global__ void __launch_bounds__(256) k_hfinal(const float* __restrict__ x,
                                                float* __restrict__ out) {
    __shared__ float sps[10*HSEGP];      // 25.6 KB
    __shared__ float swt[10*NSEGS];      // warp totals -> exclusive prefix
    int row = blockIdx.y;
    int c0  = blockIdx.x * HB;
    int s0  = c0 - RG;
    int t = threadIdx.x, lane = t & 31, w = t >> 5;

    // phase 1: bulk load 10 x HSEGP (zero-padded), 25 independent coalesced loads
    const float* __restrict__ vs = g_vsum + row * WW;
#pragma unroll
    for (int i = 0; i < 25; i++) {
        int idx = i * 256 + t;           // < 6400
        int pl  = idx / HSEGP;
        int L   = idx - pl * HSEGP;
        int gc  = s0 + L;
        float v = 0.f;
        if (L < HSEG && gc >= 0 && gc < WW) v = vs[pl * HWT + gc];
        sps[idx] = v;
    }
    __syncthreads();

    // phase 2: 200 independent warp-local inclusive scans (25 per warp)
#pragma unroll
    for (int i = 0; i < 25; i++) {
        int seg = i * 8 + w;             // < 200
        int idx = seg * 32 + lane;
        float v = sps[idx];
#pragma unroll
        for (int o = 1; o < 32; o <<= 1) {
            float n = __shfl_up_sync(0xffffffffu, v, o);
            if (lane >= o) v += n;
        }
        sps[idx] = v;
        if (lane == 31) swt[seg] = v;
    }
    __syncthreads();

    // phase 2b: per plane, exclusive prefix of its 20 warp totals
#pragma unroll
    for (int rep = 0; rep < 2; rep++) {
        int pl = rep * 8 + w;
        if (pl < 10) {
            float v = (lane < NSEGS) ? swt[pl * NSEGS + lane] : 0.f;
#pragma unroll
            for (int o = 1; o < 32; o <<= 1) {
                float n = __shfl_up_sync(0xffffffffu, v, o);
                if (lane >= o) v += n;
            }
            float e = __shfl_up_sync(0xffffffffu, v, 1);
            if (lane == 0) e = 0.f;
            if (lane < NSEGS) swt[pl * NSEGS + lane] = e;
        }
    }
    __syncthreads();

    // phase 3: windowed diff + epilogue (2 outputs per thread)
    float avg = g_avg;
    float kap = OMEGA * g_invavg;
    int ny = min(row + RG, HH - 1) - max(row - RG, 0) + 1;
#pragma unroll
    for (int j = 0; j < 2; j++) {
        int L = t + j * 256;             // 0..511
        int gc = c0 + L;
        int hi = L + 2*RG;               // <= 631
        int lo = L - 1;
        int jhi = hi >> 5;
        int jlo = (lo >= 0) ? (lo >> 5) : 0;
        float wv[10];
#pragma unroll
        for (int p = 0; p < 10; p++) {
            float sum = sps[p*HSEGP + hi] + swt[p*NSEGS + jhi];
            if (lo >= 0) sum -= sps[p*HSEGP + lo] + swt[p*NSEGS + jlo];
            wv[p] = sum;
        }
        int nx = min(gc + RG, WW - 1) - max(gc - RG, 0) + 1;
        float invN = __fdividef(1.0f, (float)(nx * ny));
        float mdc = wv[0] * invN;
        float mp  = 1.0f - kap * mdc;
        int base = row * WW + gc;
#pragma unroll
        for (int ch = 0; ch < 3; ch++) {
            float mi   = wv[1 + ch] * invN;
            float mdci = wv[4 + ch] * invN;
            float mii  = wv[7 + ch] * invN;
            float mpi  = mi - kap * mdci;
            float cip = mpi - mp * mi;
            float cii = mii - mi * mi;
            float a = __fdividef(cip, cii + EPSG);
            float b = mp - a * mi;
            float xi = x[ch * HWT + base];
            float rt = fminf(fmaxf(a * xi + b, 0.0f), 1.0f);
            rt = fmaxf(rt, 0.1f);
            float yv = __fdividef(xi - avg, rt) + avg;
            out[ch * HWT + base] = fminf(fmaxf(yv, 0.0f), 1.0f);
        }
    }
}

// ---------------- launch ----------------
extern "C" void kernel_launch(void* const* d_in, const int* in_sizes, int n_in,
                              void* d_out, int out_size) {
    const float* x = (const float*)d_in[0];
    float* out = (float*)d_out;

    k_init<<<2048, 256>>>();
    k_cmin_hmin<<<dim3(8, 2048), 256>>>(x);
    k_vmin_hist<<<dim3(8, 128), 256>>>();
    k_vpass<<<dim3(8, 64), 256>>>(x);      // launch #4 — lands in the ncu window
    k_scan1<<<1, 256>>>();
    k_hist2<<<1024, 256>>>();
    k_chunks<<<1024, 128>>>();
    k_scan2<<<1, 1024>>>();
    k_mask<<<1024, 256>>>(x);
    k_avg<<<1, 1>>>();
    k_hfinal<<<dim3(4, 2048), 256>>>(x, out);
}